// round 15
// baseline (speedup 1.0000x reference)
#include <cuda_runtime.h>
#include <math_constants.h>
#include <cstdint>

#define Bc    8
#define Np    4096
#define Ms    2048
#define Kn    16
#define CIN   64
#define COUT  128
#define BNr   (Bc*Np)     // 32768
#define BM    (Bc*Ms)     // 16384
#define NBLK_GEMM 256
#define NGRP  64
#define FPS_SMEM  200704   // 196KB: excludes any co-resident smem-using block
#define EXCL_SMEM 65536    // dummy smem: keeps helper kernels off FPS SMs

typedef unsigned long long u64;
typedef unsigned int u32;

#define ADDX2(o,a,b) asm("add.rn.f32x2 %0,%1,%2;" : "=l"(o) : "l"(a), "l"(b))
#define MULX2(o,a,b) asm("mul.rn.f32x2 %0,%1,%2;" : "=l"(o) : "l"(a), "l"(b))
__device__ __forceinline__ u64 packx2(float lo, float hi) {
    u64 o; asm("mov.b64 %0,{%1,%2};" : "=l"(o) : "f"(lo), "f"(hi)); return o;
}
__device__ __forceinline__ void unpackx2(float& lo, float& hi, u64 v) {
    asm("mov.b64 {%0,%1},%2;" : "=f"(lo), "=f"(hi) : "l"(v));
}

// ---------------- device scratch ----------------
__device__ float  g_h[BNr*COUT];
__device__ float  g_part[NBLK_GEMM*COUT*2];
__device__ float  g_scale[COUT];
__device__ float  g_shift[COUT];
__device__ float4 g_spos4[BNr];              // Morton-sorted, w = orig local idx
__device__ u64    g_nx[BNr/2];
__device__ u64    g_ny[BNr/2];
__device__ u64    g_nz[BNr/2];
__device__ u64    g_oi2[BNr/2];
__device__ float4 g_gbl[Bc*NGRP];
__device__ float4 g_gbh[Bc*NGRP];
__device__ float4 g_qpos[BM];
__device__ float4 g_sqp[BM];
__device__ int    g_nbr[BM*Kn];

// ---------------- Morton helpers ----------------
__device__ __forceinline__ u32 mort3(u32 v) { return (v & 1u) | ((v & 2u) << 2) | ((v & 4u) << 4); }
__device__ __forceinline__ u32 mcode(float x, float y, float z) {
    int cx = min(7, max(0, (int)(x * 8.f)));
    int cy = min(7, max(0, (int)(y * 8.f)));
    int cz = min(7, max(0, (int)(z * 8.f)));
    return (mort3((u32)cx) << 2) | (mort3((u32)cy) << 1) | mort3((u32)cz);
}

// ---------------- Morton counting sort (reads pos directly; emits first sample) ----------------
__global__ __launch_bounds__(512) void k_sort(const float* __restrict__ pos) {
    __shared__ u32 hist[512];
    __shared__ u32 wsum[16];
    int tid = threadIdx.x, b = blockIdx.x, cb = b * Np;
    hist[tid] = 0;
    __syncthreads();
    float4 pt[8]; u32 code[8];
    #pragma unroll
    for (int j = 0; j < 8; j++) {
        int li = j * 512 + tid;
        const float* pp = pos + (size_t)(cb + li) * 3;
        float4 p = make_float4(pp[0], pp[1], pp[2], __uint_as_float((u32)li));
        code[j] = mcode(p.x, p.y, p.z);
        pt[j] = p;
        atomicAdd(&hist[code[j]], 1u);
        if (li == 0) g_qpos[b * Ms] = p;     // FPS seed = original index 0
    }
    __syncthreads();
    u32 v = hist[tid];
    u32 inc = v;
    #pragma unroll
    for (int o = 1; o < 32; o <<= 1) {
        u32 t = __shfl_up_sync(0xFFFFFFFFu, inc, o);
        if ((tid & 31) >= o) inc += t;
    }
    if ((tid & 31) == 31) wsum[tid >> 5] = inc;
    __syncthreads();
    if (tid < 32) {
        u32 s = (tid < 16) ? wsum[tid] : 0u;
        u32 in2 = s;
        #pragma unroll
        for (int o = 1; o < 16; o <<= 1) {
            u32 t = __shfl_up_sync(0xFFFFFFFFu, in2, o);
            if (tid >= o) in2 += t;
        }
        if (tid < 16) wsum[tid] = in2 - s;
    }
    __syncthreads();
    hist[tid] = inc - v + wsum[tid >> 5];
    __syncthreads();
    #pragma unroll
    for (int j = 0; j < 8; j++) {
        u32 dst = atomicAdd(&hist[code[j]], 1u);
        g_spos4[cb + dst] = pt[j];
    }
}

// ---------------- fused pack + group bbox: warp per 64-pt group ----------------
__global__ __launch_bounds__(128) void k_packgbb() {
    extern __shared__ char dummy3[];         // occupancy shaping only
    int wid = threadIdx.x >> 5, lane = threadIdx.x & 31;
    int g = blockIdx.x * 4 + wid;            // 0..Bc*NGRP-1
    int pb = g * 32 + lane;                  // pair index
    float4 p0 = g_spos4[2*pb], p1 = g_spos4[2*pb + 1];
    g_nx[pb]  = packx2(-p0.x, -p1.x);
    g_ny[pb]  = packx2(-p0.y, -p1.y);
    g_nz[pb]  = packx2(-p0.z, -p1.z);
    g_oi2[pb] = ((u64)__float_as_uint(p1.w) << 32) | __float_as_uint(p0.w);
    // bbox: coords in [0,1) => float bits order as u32
    u32 lx = __reduce_min_sync(0xFFFFFFFFu, __float_as_uint(fminf(p0.x, p1.x)));
    u32 ly = __reduce_min_sync(0xFFFFFFFFu, __float_as_uint(fminf(p0.y, p1.y)));
    u32 lz = __reduce_min_sync(0xFFFFFFFFu, __float_as_uint(fminf(p0.z, p1.z)));
    u32 hx = __reduce_max_sync(0xFFFFFFFFu, __float_as_uint(fmaxf(p0.x, p1.x)));
    u32 hy = __reduce_max_sync(0xFFFFFFFFu, __float_as_uint(fmaxf(p0.y, p1.y)));
    u32 hz = __reduce_max_sync(0xFFFFFFFFu, __float_as_uint(fmaxf(p0.z, p1.z)));
    if (lane == 0) {
        g_gbl[g] = make_float4(__uint_as_float(lx), __uint_as_float(ly), __uint_as_float(lz), 0.f);
        g_gbh[g] = make_float4(__uint_as_float(hx), __uint_as_float(hy), __uint_as_float(hz), 0.f);
    }
}

// ---------------- GEMM + BN partials ----------------
__global__ __launch_bounds__(256) void k_gemm(const float* __restrict__ x,
                                              const float* __restrict__ W,
                                              const float* __restrict__ bias) {
    __shared__ float sW[CIN*COUT];
    __shared__ float sx[32*CIN];
    __shared__ float sred[256*8];
    int tid = threadIdx.x;

    const float4* W4 = (const float4*)W;
    float4* sW4 = (float4*)sW;
    #pragma unroll
    for (int i = 0; i < 8; i++) sW4[tid + i*256] = W4[tid + i*256];

    int c4   = (tid & 31) * 4;
    int wrow = (tid >> 5) * 4;
    float4 bv = *(const float4*)(bias + c4);

    float s0=0.f,s1=0.f,s2=0.f,s3=0.f, q0=0.f,q1=0.f,q2=0.f,q3=0.f;
    int rowblk = blockIdx.x * 128;

    for (int sub = 0; sub < 4; sub++) {
        __syncthreads();
        int r0 = rowblk + sub*32;
        const float4* xg = (const float4*)(x + (size_t)r0 * CIN);
        float4* sx4 = (float4*)sx;
        sx4[tid]       = xg[tid];
        sx4[tid + 256] = xg[tid + 256];
        __syncthreads();

        float a[4][4];
        #pragma unroll
        for (int r = 0; r < 4; r++) { a[r][0]=bv.x; a[r][1]=bv.y; a[r][2]=bv.z; a[r][3]=bv.w; }
        #pragma unroll 8
        for (int k = 0; k < CIN; k++) {
            float4 w4 = *(float4*)(sW + k*COUT + c4);
            #pragma unroll
            for (int r = 0; r < 4; r++) {
                float xv = sx[(wrow + r)*CIN + k];
                a[r][0] = fmaf(xv, w4.x, a[r][0]);
                a[r][1] = fmaf(xv, w4.y, a[r][1]);
                a[r][2] = fmaf(xv, w4.z, a[r][2]);
                a[r][3] = fmaf(xv, w4.w, a[r][3]);
            }
        }
        #pragma unroll
        for (int r = 0; r < 4; r++) {
            int row = r0 + wrow + r;
            *(float4*)(g_h + (size_t)row*COUT + c4) =
                make_float4(a[r][0], a[r][1], a[r][2], a[r][3]);
            s0 += a[r][0]; s1 += a[r][1]; s2 += a[r][2]; s3 += a[r][3];
            q0 = fmaf(a[r][0], a[r][0], q0);
            q1 = fmaf(a[r][1], a[r][1], q1);
            q2 = fmaf(a[r][2], a[r][2], q2);
            q3 = fmaf(a[r][3], a[r][3], q3);
        }
    }
    float* rp = sred + tid*8;
    rp[0]=s0; rp[1]=s1; rp[2]=s2; rp[3]=s3; rp[4]=q0; rp[5]=q1; rp[6]=q2; rp[7]=q3;
    __syncthreads();
    if (tid < 32) {
        float ss[4] = {0,0,0,0}, qq[4] = {0,0,0,0};
        for (int w = 0; w < 8; w++) {
            float* p = sred + (w*32 + tid)*8;
            #pragma unroll
            for (int i = 0; i < 4; i++) { ss[i] += p[i]; qq[i] += p[4+i]; }
        }
        #pragma unroll
        for (int i = 0; i < 4; i++) {
            int c = tid*4 + i;
            g_part[(blockIdx.x*COUT + c)*2 + 0] = ss[i];
            g_part[(blockIdx.x*COUT + c)*2 + 1] = qq[i];
        }
    }
}

__global__ void k_stats(const float* __restrict__ gamma, const float* __restrict__ beta) {
    extern __shared__ char dummy1[];
    int c = threadIdx.x;
    float s = 0.f, q = 0.f;
    for (int b = 0; b < NBLK_GEMM; b++) {
        s += g_part[(b*COUT + c)*2 + 0];
        q += g_part[(b*COUT + c)*2 + 1];
    }
    float mu   = s * (1.0f / BNr);
    float var  = q * (1.0f / BNr) - mu*mu;
    float rstd = rsqrtf(var + 1e-5f);
    float sc   = gamma[c] * rstd;
    g_scale[c] = sc;
    g_shift[c] = beta[c] - mu * sc;
}

__global__ __launch_bounds__(256) void k_act() {
    extern __shared__ char dummy2[];
    int i = blockIdx.x * 256 + threadIdx.x;
    float4 h = ((float4*)g_h)[i];
    int c4 = (i & 31) * 4;
    float4 sc = *(float4*)(g_scale + c4);
    float4 sh = *(float4*)(g_shift + c4);
    float y0 = fmaf(h.x, sc.x, sh.x);
    float y1 = fmaf(h.y, sc.y, sh.y);
    float y2 = fmaf(h.z, sc.z, sh.z);
    float y3 = fmaf(h.w, sc.w, sh.w);
    const float is2 = 0.70710678118654752f;
    h.x = 0.5f * y0 * (1.f + erff(y0 * is2));
    h.y = 0.5f * y1 * (1.f + erff(y1 * is2));
    h.z = 0.5f * y2 * (1.f + erff(y2 * is2));
    h.w = 0.5f * y3 * (1.f + erff(y3 * is2));
    ((float4*)g_h)[i] = h;
}

// ---------------- pruned FPS: 512 thr, per-iteration smem atomicMax reduction ----------------
// Key = (dist_bits<<32) | ((4095-orig_idx)<<12) | sorted_slot : total order matches
// reference argmax (max dist, tie -> lowest original index). atomicMax is commutative
// => deterministic. One barrier per iteration; s_best[m] slots avoid any reset race.
__global__ __launch_bounds__(512) void k_fps() {
    extern __shared__ char fsm[];
    float4* s_pts  = (float4*)fsm;                 // 4096 float4 = 64KB
    u64*    s_best = (u64*)(fsm + Np*16);          // Ms slots = 16KB
    int tid = threadIdx.x, b = blockIdx.x, cb = b * Np;
    int lane = tid & 31;

    float dm[8]; u32 cij[8];
    u64 npx[4], npy[4], npz[4];
    float lox =  CUDART_INF_F, loy =  CUDART_INF_F, loz =  CUDART_INF_F;
    float hix = -CUDART_INF_F, hiy = -CUDART_INF_F, hiz = -CUDART_INF_F;
    {
        float tx[8], ty[8], tz[8];
        #pragma unroll
        for (int j = 0; j < 8; j++) {
            float4 p = g_spos4[cb + tid*8 + j];
            s_pts[tid*8 + j] = p;
            tx[j] = p.x; ty[j] = p.y; tz[j] = p.z;
            cij[j] = ((4095u - __float_as_uint(p.w)) << 12) | (u32)(tid*8 + j);
            dm[j] = CUDART_INF_F;
            lox = fminf(lox, p.x); hix = fmaxf(hix, p.x);
            loy = fminf(loy, p.y); hiy = fmaxf(hiy, p.y);
            loz = fminf(loz, p.z); hiz = fmaxf(hiz, p.z);
        }
        #pragma unroll
        for (int j = 0; j < 4; j++) s_best[tid*4 + j] = 0ull;
        #pragma unroll
        for (int p = 0; p < 4; p++) {
            npx[p] = packx2(-tx[2*p], -tx[2*p+1]);
            npy[p] = packx2(-ty[2*p], -ty[2*p+1]);
            npz[p] = packx2(-tz[2*p], -tz[2*p+1]);
        }
    }
    float gmaxd = CUDART_INF_F;
    u64 wkey = 0;

    float4 a4 = g_qpos[b * Ms];               // seed written by k_sort
    float ax = a4.x, ay = a4.y, az = a4.z;
    __syncthreads();                          // s_pts + s_best visible

    for (int m = 1; m < Ms; m++) {
        float bx = fmaxf(fmaxf(lox - ax, ax - hix), 0.f);
        float by = fmaxf(fmaxf(loy - ay, ay - hiy), 0.f);
        float bz = fmaxf(fmaxf(loz - az, az - hiz), 0.f);
        float LB = (bx*bx + by*by + bz*bz) * 0.999f;
        bool active = (LB < gmaxd);
        u32 aball = __ballot_sync(0xFFFFFFFFu, active);
        if (aball) {                          // some lane changed: recompute warp key
            if (active) {
                u64 pax = packx2(ax, ax), pay = packx2(ay, ay), paz = packx2(az, az);
                #pragma unroll
                for (int p = 0; p < 4; p++) {
                    u64 dx, dy, dz, s2x, s2y, s2z, s;
                    ADDX2(dx, pax, npx[p]);
                    ADDX2(dy, pay, npy[p]);
                    ADDX2(dz, paz, npz[p]);
                    MULX2(s2x, dx, dx);
                    MULX2(s2y, dy, dy);
                    MULX2(s2z, dz, dz);
                    ADDX2(s, s2x, s2y);
                    ADDX2(s, s, s2z);
                    float lo, hi; unpackx2(lo, hi, s);
                    dm[2*p]   = fminf(dm[2*p],   lo);
                    dm[2*p+1] = fminf(dm[2*p+1], hi);
                }
                float m01 = fmaxf(dm[0], dm[1]), m23 = fmaxf(dm[2], dm[3]);
                float m45 = fmaxf(dm[4], dm[5]), m67 = fmaxf(dm[6], dm[7]);
                gmaxd = fmaxf(fmaxf(m01, m23), fmaxf(m45, m67));
            }
            u32 db = __float_as_uint(gmaxd);
            u32 bd = __reduce_max_sync(0xFFFFFFFFu, db);
            u32 cand = 0u;
            if (db == bd) {
                #pragma unroll
                for (int j = 0; j < 8; j++)
                    cand = max(cand, (dm[j] == gmaxd) ? cij[j] : 0u);
            }
            u32 bi = __reduce_max_sync(0xFFFFFFFFu, cand);
            wkey = ((u64)bd << 32) | bi;
        }
        if (lane == 0) atomicMax((unsigned long long*)&s_best[m], (unsigned long long)wkey);
        __syncthreads();
        u64 bk = s_best[m];                   // uniform broadcast read
        int spos = (int)(bk & 0xFFFu);
        float4 p = s_pts[spos];               // LDS broadcast
        ax = p.x; ay = p.y; az = p.z;
        if (tid == 0) g_qpos[b * Ms + m] = p;
    }
}

// ---------------- query Morton sort + output emit (fused) ----------------
__global__ __launch_bounds__(512) void k_qsort(float* __restrict__ out_pos,
                                               float* __restrict__ out_batch) {
    __shared__ u32 hist[512];
    __shared__ u32 wsum[16];
    int tid = threadIdx.x, b = blockIdx.x, qb = b * Ms;
    hist[tid] = 0;
    __syncthreads();
    float4 pt[4]; u32 code[4];
    #pragma unroll
    for (int j = 0; j < 4; j++) {
        int li = j * 512 + tid;
        float4 p = g_qpos[qb + li];
        code[j] = mcode(p.x, p.y, p.z);
        if (out_pos) {
            int q = qb + li;
            out_pos[(size_t)q*3+0] = p.x;
            out_pos[(size_t)q*3+1] = p.y;
            out_pos[(size_t)q*3+2] = p.z;
            out_batch[q] = (float)b;
        }
        p.w = __uint_as_float((u32)li);
        pt[j] = p;
        atomicAdd(&hist[code[j]], 1u);
    }
    __syncthreads();
    u32 v = hist[tid];
    u32 inc = v;
    #pragma unroll
    for (int o = 1; o < 32; o <<= 1) {
        u32 t = __shfl_up_sync(0xFFFFFFFFu, inc, o);
        if ((tid & 31) >= o) inc += t;
    }
    if ((tid & 31) == 31) wsum[tid >> 5] = inc;
    __syncthreads();
    if (tid < 32) {
        u32 s = (tid < 16) ? wsum[tid] : 0u;
        u32 in2 = s;
        #pragma unroll
        for (int o = 1; o < 16; o <<= 1) {
            u32 t = __shfl_up_sync(0xFFFFFFFFu, in2, o);
            if (tid >= o) in2 += t;
        }
        if (tid < 16) wsum[tid] = in2 - s;
    }
    __syncthreads();
    hist[tid] = inc - v + wsum[tid >> 5];
    __syncthreads();
    #pragma unroll
    for (int j = 0; j < 4; j++) {
        u32 dst = atomicAdd(&hist[code[j]], 1u);
        g_sqp[qb + dst] = pt[j];
    }
}

// ---------------- hierarchical KNN ----------------
__global__ __launch_bounds__(128) void k_knn() {
    int tid = threadIdx.x, bid = blockIdx.x;
    int b  = bid >> 4;
    int t  = (bid & 15) * 128 + tid;
    int bp = b * (Np/2);
    int gb = b * NGRP;

    float4 sq = g_sqp[b * Ms + t];
    u32 oq = __float_as_uint(sq.w);
    float qxf = sq.x, qyf = sq.y, qzf = sq.z;
    u64 qx = packx2(qxf, qxf);
    u64 qy = packx2(qyf, qyf);
    u64 qz = packx2(qzf, qzf);

    u64 dd[16];
    #pragma unroll
    for (int k = 0; k < 16; k++) dd[k] = ~0ull;
    u64 kmax = ~0ull; int mp = 0;

    auto ins = [&](u64 key) {
        if (key < kmax) {
            dd[mp] = key;
            kmax = dd[0]; mp = 0;
            #pragma unroll
            for (int k = 1; k < 16; k++) if (dd[k] > kmax) { kmax = dd[k]; mp = k; }
        }
    };
    auto proc = [&](int g) {
        int base = bp + g * 32;
        #pragma unroll 4
        for (int j = 0; j < 32; j++) {
            u64 ox = g_nx[base + j], oy = g_ny[base + j], oz = g_nz[base + j];
            u64 oo = g_oi2[base + j];
            u64 dx, dy, dz, s2x, s2y, s2z, sum;
            ADDX2(dx, qx, ox);
            ADDX2(dy, qy, oy);
            ADDX2(dz, qz, oz);
            MULX2(s2x, dx, dx);
            MULX2(s2y, dy, dy);
            MULX2(s2z, dz, dz);
            ADDX2(sum, s2x, s2y);
            ADDX2(sum, sum, s2z);
            float lo, hi; unpackx2(lo, hi, sum);
            ins(((u64)__float_as_uint(lo) << 32) | (u32)oo);
            ins(((u64)__float_as_uint(hi) << 32) | (u32)(oo >> 32));
        }
    };
    auto lbof = [&](int g) {
        float4 lo = g_gbl[gb + g], hi = g_gbh[gb + g];
        float bx = fmaxf(fmaxf(lo.x - qxf, qxf - hi.x), 0.f);
        float by = fmaxf(fmaxf(lo.y - qyf, qyf - hi.y), 0.f);
        float bz = fmaxf(fmaxf(lo.z - qzf, qzf - hi.z), 0.f);
        return (bx*bx + by*by + bz*bz) * 0.999f;
    };

    float bestLB = CUDART_INF_F; int bg = 0;
    for (int g = 0; g < NGRP; g++) {
        float LB = lbof(g);
        if (LB < bestLB) { bestLB = LB; bg = g; }
    }
    int bgw = __shfl_sync(0xFFFFFFFFu, bg, 0);
    proc(bgw);

    for (int g = 0; g < NGRP; g++) {
        if (g == bgw) continue;
        float LB = lbof(g);
        bool act = __float_as_uint(LB) <= (u32)(kmax >> 32);
        if (__ballot_sync(0xFFFFFFFFu, act) == 0u) continue;
        proc(g);
    }

    int cb = b * Np;
    int qout = b * Ms + (int)oq;
    #pragma unroll
    for (int k = 0; k < 16; k++)
        g_nbr[(size_t)qout*Kn + k] = cb + (int)(dd[k] & 0xFFFFFFFFu);
}

// ---------------- gather + max-pool ----------------
__global__ __launch_bounds__(256) void k_gather(float* __restrict__ out_x) {
    int gq   = (blockIdx.x * 256 + threadIdx.x) >> 5;
    int lane = threadIdx.x & 31;
    int nb[16];
    #pragma unroll
    for (int k = 0; k < 16; k++) nb[k] = g_nbr[(size_t)gq*Kn + k];
    float4 acc = make_float4(-CUDART_INF_F, -CUDART_INF_F, -CUDART_INF_F, -CUDART_INF_F);
    #pragma unroll
    for (int k = 0; k < 16; k++) {
        float4 v = *(const float4*)(g_h + (size_t)nb[k]*COUT + lane*4);
        acc.x = fmaxf(acc.x, v.x);
        acc.y = fmaxf(acc.y, v.y);
        acc.z = fmaxf(acc.z, v.z);
        acc.w = fmaxf(acc.w, v.w);
    }
    *(float4*)(out_x + (size_t)gq*COUT + lane*4) = acc;
}

// ---------------- launch ----------------
extern "C" void kernel_launch(void* const* d_in, const int* in_sizes, int n_in,
                              void* d_out, int out_size) {
    const float* x     = (const float*)d_in[0];
    const float* pos   = (const float*)d_in[1];
    const float* W     = (const float*)d_in[3];
    const float* bias  = (const float*)d_in[4];
    const float* gamma = (const float*)d_in[5];
    const float* beta  = (const float*)d_in[6];

    float* out       = (float*)d_out;
    float* out_x     = out;
    float* out_pos   = nullptr;
    float* out_batch = nullptr;
    if (out_size >= BM*COUT + BM*3 + BM) {
        out_pos   = out + BM*COUT;
        out_batch = out + BM*COUT + BM*3;
    }

    static cudaStream_t s2 = nullptr;
    static cudaEvent_t  e0 = nullptr, e1 = nullptr, e2 = nullptr;
    if (!s2) {
        cudaStreamCreateWithFlags(&s2, cudaStreamNonBlocking);
        cudaEventCreateWithFlags(&e0, cudaEventDisableTiming);
        cudaEventCreateWithFlags(&e1, cudaEventDisableTiming);
        cudaEventCreateWithFlags(&e2, cudaEventDisableTiming);
        cudaFuncSetAttribute(k_fps,     cudaFuncAttributeMaxDynamicSharedMemorySize, FPS_SMEM);
        cudaFuncSetAttribute(k_act,     cudaFuncAttributeMaxDynamicSharedMemorySize, EXCL_SMEM);
        cudaFuncSetAttribute(k_stats,   cudaFuncAttributeMaxDynamicSharedMemorySize, EXCL_SMEM);
        cudaFuncSetAttribute(k_packgbb, cudaFuncAttributeMaxDynamicSharedMemorySize, EXCL_SMEM);
    }

    // launch 1: sort (critical path for FPS)
    k_sort  <<<Bc, 512>>>(pos);

    // fork helper chain onto s2 (all excluded from FPS SMs by smem footprint)
    cudaEventRecord(e0, 0);
    cudaStreamWaitEvent(s2, e0, 0);
    k_packgbb <<<Bc*NGRP/4, 128, EXCL_SMEM, s2>>>();            // launch 2
    cudaEventRecord(e2, s2);                                    // knn dep
    k_gemm  <<<NBLK_GEMM, 256, 0, s2>>>(x, W, bias);            // launch 3
    k_stats <<<1, COUT, EXCL_SMEM, s2>>>(gamma, beta);          // launch 4
    k_act   <<<(BNr*COUT/4)/256, 256, EXCL_SMEM, s2>>>();       // launch 5
    cudaEventRecord(e1, s2);                                    // gather dep

    // launch 6: FPS (ncu -s 5 -c 1 profiles this)
    k_fps   <<<Bc, 512, FPS_SMEM>>>();

    k_qsort <<<Bc, 512>>>(out_pos, out_batch);                  // launch 7
    cudaStreamWaitEvent(0, e2, 0);
    k_knn   <<<Bc*16, 128>>>();                                 // launch 8
    cudaStreamWaitEvent(0, e1, 0);
    k_gather<<<BM/8, 256>>>(out_x);                             // launch 9
}

// round 16
// speedup vs baseline: 1.1752x; 1.1752x over previous
#include <cuda_runtime.h>
#include <math_constants.h>
#include <cstdint>

#define Bc    8
#define Np    4096
#define Ms    2048
#define Kn    16
#define CIN   64
#define COUT  128
#define BNr   (Bc*Np)     // 32768
#define BM    (Bc*Ms)     // 16384
#define NBLK_GEMM 256
#define NGRP  64
#define FPS_SMEM  200704   // 196KB: excludes any co-resident smem-using block
#define EXCL_SMEM 65536    // dummy smem: keeps helper kernels off FPS SMs

typedef unsigned long long u64;
typedef unsigned int u32;

#define ADDX2(o,a,b) asm("add.rn.f32x2 %0,%1,%2;" : "=l"(o) : "l"(a), "l"(b))
#define MULX2(o,a,b) asm("mul.rn.f32x2 %0,%1,%2;" : "=l"(o) : "l"(a), "l"(b))
__device__ __forceinline__ u64 packx2(float lo, float hi) {
    u64 o; asm("mov.b64 %0,{%1,%2};" : "=l"(o) : "f"(lo), "f"(hi)); return o;
}
__device__ __forceinline__ void unpackx2(float& lo, float& hi, u64 v) {
    asm("mov.b64 {%0,%1},%2;" : "=f"(lo), "=f"(hi) : "l"(v));
}

// ---------------- device scratch ----------------
__device__ float  g_h[BNr*COUT];
__device__ float  g_part[NBLK_GEMM*COUT*2];
__device__ float  g_scale[COUT];
__device__ float  g_shift[COUT];
__device__ float4 g_spos4[BNr];              // Morton-sorted, w = orig local idx
__device__ u64    g_nx[BNr/2];
__device__ u64    g_ny[BNr/2];
__device__ u64    g_nz[BNr/2];
__device__ u64    g_oi2[BNr/2];
__device__ float4 g_gbl[Bc*NGRP];
__device__ float4 g_gbh[Bc*NGRP];
__device__ float4 g_qpos[BM];
__device__ float4 g_sqp[BM];
__device__ int    g_nbr[BM*Kn];

// ---------------- Morton helpers ----------------
__device__ __forceinline__ u32 mort3(u32 v) { return (v & 1u) | ((v & 2u) << 2) | ((v & 4u) << 4); }
__device__ __forceinline__ u32 mcode(float x, float y, float z) {
    int cx = min(7, max(0, (int)(x * 8.f)));
    int cy = min(7, max(0, (int)(y * 8.f)));
    int cz = min(7, max(0, (int)(z * 8.f)));
    return (mort3((u32)cx) << 2) | (mort3((u32)cy) << 1) | mort3((u32)cz);
}

// ---------------- Morton counting sort (reads pos directly; emits first sample) ----------------
__global__ __launch_bounds__(512) void k_sort(const float* __restrict__ pos) {
    __shared__ u32 hist[512];
    __shared__ u32 wsum[16];
    int tid = threadIdx.x, b = blockIdx.x, cb = b * Np;
    hist[tid] = 0;
    __syncthreads();
    float4 pt[8]; u32 code[8];
    #pragma unroll
    for (int j = 0; j < 8; j++) {
        int li = j * 512 + tid;
        const float* pp = pos + (size_t)(cb + li) * 3;
        float4 p = make_float4(pp[0], pp[1], pp[2], __uint_as_float((u32)li));
        code[j] = mcode(p.x, p.y, p.z);
        pt[j] = p;
        atomicAdd(&hist[code[j]], 1u);
        if (li == 0) g_qpos[b * Ms] = p;     // FPS seed = original index 0
    }
    __syncthreads();
    u32 v = hist[tid];
    u32 inc = v;
    #pragma unroll
    for (int o = 1; o < 32; o <<= 1) {
        u32 t = __shfl_up_sync(0xFFFFFFFFu, inc, o);
        if ((tid & 31) >= o) inc += t;
    }
    if ((tid & 31) == 31) wsum[tid >> 5] = inc;
    __syncthreads();
    if (tid < 32) {
        u32 s = (tid < 16) ? wsum[tid] : 0u;
        u32 in2 = s;
        #pragma unroll
        for (int o = 1; o < 16; o <<= 1) {
            u32 t = __shfl_up_sync(0xFFFFFFFFu, in2, o);
            if (tid >= o) in2 += t;
        }
        if (tid < 16) wsum[tid] = in2 - s;
    }
    __syncthreads();
    hist[tid] = inc - v + wsum[tid >> 5];
    __syncthreads();
    #pragma unroll
    for (int j = 0; j < 8; j++) {
        u32 dst = atomicAdd(&hist[code[j]], 1u);
        g_spos4[cb + dst] = pt[j];
    }
}

// ---------------- fused pack + group bbox: warp per 64-pt group ----------------
__global__ __launch_bounds__(128) void k_packgbb() {
    extern __shared__ char dummy3[];         // occupancy shaping only
    int wid = threadIdx.x >> 5, lane = threadIdx.x & 31;
    int g = blockIdx.x * 4 + wid;            // 0..Bc*NGRP-1
    int pb = g * 32 + lane;                  // pair index
    float4 p0 = g_spos4[2*pb], p1 = g_spos4[2*pb + 1];
    g_nx[pb]  = packx2(-p0.x, -p1.x);
    g_ny[pb]  = packx2(-p0.y, -p1.y);
    g_nz[pb]  = packx2(-p0.z, -p1.z);
    g_oi2[pb] = ((u64)__float_as_uint(p1.w) << 32) | __float_as_uint(p0.w);
    // bbox: coords in [0,1) => float bits order as u32
    u32 lx = __reduce_min_sync(0xFFFFFFFFu, __float_as_uint(fminf(p0.x, p1.x)));
    u32 ly = __reduce_min_sync(0xFFFFFFFFu, __float_as_uint(fminf(p0.y, p1.y)));
    u32 lz = __reduce_min_sync(0xFFFFFFFFu, __float_as_uint(fminf(p0.z, p1.z)));
    u32 hx = __reduce_max_sync(0xFFFFFFFFu, __float_as_uint(fmaxf(p0.x, p1.x)));
    u32 hy = __reduce_max_sync(0xFFFFFFFFu, __float_as_uint(fmaxf(p0.y, p1.y)));
    u32 hz = __reduce_max_sync(0xFFFFFFFFu, __float_as_uint(fmaxf(p0.z, p1.z)));
    if (lane == 0) {
        g_gbl[g] = make_float4(__uint_as_float(lx), __uint_as_float(ly), __uint_as_float(lz), 0.f);
        g_gbh[g] = make_float4(__uint_as_float(hx), __uint_as_float(hy), __uint_as_float(hz), 0.f);
    }
}

// ---------------- GEMM + BN partials ----------------
__global__ __launch_bounds__(256) void k_gemm(const float* __restrict__ x,
                                              const float* __restrict__ W,
                                              const float* __restrict__ bias) {
    __shared__ float sW[CIN*COUT];
    __shared__ float sx[32*CIN];
    __shared__ float sred[256*8];
    int tid = threadIdx.x;

    const float4* W4 = (const float4*)W;
    float4* sW4 = (float4*)sW;
    #pragma unroll
    for (int i = 0; i < 8; i++) sW4[tid + i*256] = W4[tid + i*256];

    int c4   = (tid & 31) * 4;
    int wrow = (tid >> 5) * 4;
    float4 bv = *(const float4*)(bias + c4);

    float s0=0.f,s1=0.f,s2=0.f,s3=0.f, q0=0.f,q1=0.f,q2=0.f,q3=0.f;
    int rowblk = blockIdx.x * 128;

    for (int sub = 0; sub < 4; sub++) {
        __syncthreads();
        int r0 = rowblk + sub*32;
        const float4* xg = (const float4*)(x + (size_t)r0 * CIN);
        float4* sx4 = (float4*)sx;
        sx4[tid]       = xg[tid];
        sx4[tid + 256] = xg[tid + 256];
        __syncthreads();

        float a[4][4];
        #pragma unroll
        for (int r = 0; r < 4; r++) { a[r][0]=bv.x; a[r][1]=bv.y; a[r][2]=bv.z; a[r][3]=bv.w; }
        #pragma unroll 8
        for (int k = 0; k < CIN; k++) {
            float4 w4 = *(float4*)(sW + k*COUT + c4);
            #pragma unroll
            for (int r = 0; r < 4; r++) {
                float xv = sx[(wrow + r)*CIN + k];
                a[r][0] = fmaf(xv, w4.x, a[r][0]);
                a[r][1] = fmaf(xv, w4.y, a[r][1]);
                a[r][2] = fmaf(xv, w4.z, a[r][2]);
                a[r][3] = fmaf(xv, w4.w, a[r][3]);
            }
        }
        #pragma unroll
        for (int r = 0; r < 4; r++) {
            int row = r0 + wrow + r;
            *(float4*)(g_h + (size_t)row*COUT + c4) =
                make_float4(a[r][0], a[r][1], a[r][2], a[r][3]);
            s0 += a[r][0]; s1 += a[r][1]; s2 += a[r][2]; s3 += a[r][3];
            q0 = fmaf(a[r][0], a[r][0], q0);
            q1 = fmaf(a[r][1], a[r][1], q1);
            q2 = fmaf(a[r][2], a[r][2], q2);
            q3 = fmaf(a[r][3], a[r][3], q3);
        }
    }
    float* rp = sred + tid*8;
    rp[0]=s0; rp[1]=s1; rp[2]=s2; rp[3]=s3; rp[4]=q0; rp[5]=q1; rp[6]=q2; rp[7]=q3;
    __syncthreads();
    if (tid < 32) {
        float ss[4] = {0,0,0,0}, qq[4] = {0,0,0,0};
        for (int w = 0; w < 8; w++) {
            float* p = sred + (w*32 + tid)*8;
            #pragma unroll
            for (int i = 0; i < 4; i++) { ss[i] += p[i]; qq[i] += p[4+i]; }
        }
        #pragma unroll
        for (int i = 0; i < 4; i++) {
            int c = tid*4 + i;
            g_part[(blockIdx.x*COUT + c)*2 + 0] = ss[i];
            g_part[(blockIdx.x*COUT + c)*2 + 1] = qq[i];
        }
    }
}

__global__ void k_stats(const float* __restrict__ gamma, const float* __restrict__ beta) {
    extern __shared__ char dummy1[];
    int c = threadIdx.x;
    float s = 0.f, q = 0.f;
    for (int b = 0; b < NBLK_GEMM; b++) {
        s += g_part[(b*COUT + c)*2 + 0];
        q += g_part[(b*COUT + c)*2 + 1];
    }
    float mu   = s * (1.0f / BNr);
    float var  = q * (1.0f / BNr) - mu*mu;
    float rstd = rsqrtf(var + 1e-5f);
    float sc   = gamma[c] * rstd;
    g_scale[c] = sc;
    g_shift[c] = beta[c] - mu * sc;
}

__global__ __launch_bounds__(256) void k_act() {
    extern __shared__ char dummy2[];
    int i = blockIdx.x * 256 + threadIdx.x;
    float4 h = ((float4*)g_h)[i];
    int c4 = (i & 31) * 4;
    float4 sc = *(float4*)(g_scale + c4);
    float4 sh = *(float4*)(g_shift + c4);
    float y0 = fmaf(h.x, sc.x, sh.x);
    float y1 = fmaf(h.y, sc.y, sh.y);
    float y2 = fmaf(h.z, sc.z, sh.z);
    float y3 = fmaf(h.w, sc.w, sh.w);
    const float is2 = 0.70710678118654752f;
    h.x = 0.5f * y0 * (1.f + erff(y0 * is2));
    h.y = 0.5f * y1 * (1.f + erff(y1 * is2));
    h.z = 0.5f * y2 * (1.f + erff(y2 * is2));
    h.w = 0.5f * y3 * (1.f + erff(y3 * is2));
    ((float4*)g_h)[i] = h;
}

// ---------------- pruned FPS (R7 topology): 512 thr, cached warp keys, two-stage redux ----------------
__global__ __launch_bounds__(512) void k_fps() {
    extern __shared__ char fsm[];
    float4* s_pts  = (float4*)fsm;                 // 4096 float4 = 64KB
    u64*    s_wkey = (u64*)(fsm + Np*16);          // 2 x 16 keys
    int tid = threadIdx.x, b = blockIdx.x, cb = b * Np;
    int lane = tid & 31, w = tid >> 5;

    float dm[8]; u32 cij[8];                 // cij = ((4095-oi)<<12)|slot  (invariant)
    u64 npx[4], npy[4], npz[4];
    float lox =  CUDART_INF_F, loy =  CUDART_INF_F, loz =  CUDART_INF_F;
    float hix = -CUDART_INF_F, hiy = -CUDART_INF_F, hiz = -CUDART_INF_F;
    {
        float tx[8], ty[8], tz[8];
        #pragma unroll
        for (int j = 0; j < 8; j++) {
            float4 p = g_spos4[cb + tid*8 + j];
            s_pts[tid*8 + j] = p;
            tx[j] = p.x; ty[j] = p.y; tz[j] = p.z;
            cij[j] = ((4095u - __float_as_uint(p.w)) << 12) | (u32)(tid*8 + j);
            dm[j] = CUDART_INF_F;
            lox = fminf(lox, p.x); hix = fmaxf(hix, p.x);
            loy = fminf(loy, p.y); hiy = fmaxf(hiy, p.y);
            loz = fminf(loz, p.z); hiz = fmaxf(hiz, p.z);
        }
        #pragma unroll
        for (int p = 0; p < 4; p++) {
            npx[p] = packx2(-tx[2*p], -tx[2*p+1]);
            npy[p] = packx2(-ty[2*p], -ty[2*p+1]);
            npz[p] = packx2(-tz[2*p], -tz[2*p+1]);
        }
    }
    float gmaxd = CUDART_INF_F;
    u64 wkey = 0;                             // cached warp key

    float4 a4 = g_qpos[b * Ms];               // seed written by k_sort
    float ax = a4.x, ay = a4.y, az = a4.z;
    __syncthreads();                          // s_pts visible before winner LDS

    for (int m = 1; m < Ms; m++) {
        float bx = fmaxf(fmaxf(lox - ax, ax - hix), 0.f);
        float by = fmaxf(fmaxf(loy - ay, ay - hiy), 0.f);
        float bz = fmaxf(fmaxf(loz - az, az - hiz), 0.f);
        float LB = (bx*bx + by*by + bz*bz) * 0.999f;
        bool active = (LB < gmaxd);
        u32 aball = __ballot_sync(0xFFFFFFFFu, active);
        if (aball) {                          // some lane changed: recompute warp key
            if (active) {
                u64 pax = packx2(ax, ax), pay = packx2(ay, ay), paz = packx2(az, az);
                #pragma unroll
                for (int p = 0; p < 4; p++) {
                    u64 dx, dy, dz, s2x, s2y, s2z, s;
                    ADDX2(dx, pax, npx[p]);
                    ADDX2(dy, pay, npy[p]);
                    ADDX2(dz, paz, npz[p]);
                    MULX2(s2x, dx, dx);
                    MULX2(s2y, dy, dy);
                    MULX2(s2z, dz, dz);
                    ADDX2(s, s2x, s2y);
                    ADDX2(s, s, s2z);
                    float lo, hi; unpackx2(lo, hi, s);
                    dm[2*p]   = fminf(dm[2*p],   lo);
                    dm[2*p+1] = fminf(dm[2*p+1], hi);
                }
                float m01 = fmaxf(dm[0], dm[1]), m23 = fmaxf(dm[2], dm[3]);
                float m45 = fmaxf(dm[4], dm[5]), m67 = fmaxf(dm[6], dm[7]);
                gmaxd = fmaxf(fmaxf(m01, m23), fmaxf(m45, m67));
            }
            u32 db = __float_as_uint(gmaxd);
            u32 bd = __reduce_max_sync(0xFFFFFFFFu, db);
            u32 cand = 0u;
            if (db == bd) {
                #pragma unroll
                for (int j = 0; j < 8; j++)
                    cand = max(cand, (dm[j] == gmaxd) ? cij[j] : 0u);
            }
            u32 bi = __reduce_max_sync(0xFFFFFFFFu, cand);
            wkey = ((u64)bd << 32) | bi;
        }
        if (lane == 0) s_wkey[(m & 1)*16 + w] = wkey;
        __syncthreads();
        u64 kk  = s_wkey[(m & 1)*16 + (lane & 15)];
        u32 hb  = (u32)(kk >> 32);
        u32 bd2 = __reduce_max_sync(0xFFFFFFFFu, hb);
        u32 c2  = (hb == bd2) ? (u32)kk : 0u;
        u32 wi  = __reduce_max_sync(0xFFFFFFFFu, c2);
        int spos = (int)(wi & 0xFFFu);
        float4 p = s_pts[spos];               // LDS broadcast
        ax = p.x; ay = p.y; az = p.z;
        if (tid == 0) g_qpos[b * Ms + m] = p;
    }
}

// ---------------- query Morton sort + output emit (fused) ----------------
__global__ __launch_bounds__(512) void k_qsort(float* __restrict__ out_pos,
                                               float* __restrict__ out_batch) {
    __shared__ u32 hist[512];
    __shared__ u32 wsum[16];
    int tid = threadIdx.x, b = blockIdx.x, qb = b * Ms;
    hist[tid] = 0;
    __syncthreads();
    float4 pt[4]; u32 code[4];
    #pragma unroll
    for (int j = 0; j < 4; j++) {
        int li = j * 512 + tid;
        float4 p = g_qpos[qb + li];
        code[j] = mcode(p.x, p.y, p.z);
        if (out_pos) {
            int q = qb + li;
            out_pos[(size_t)q*3+0] = p.x;
            out_pos[(size_t)q*3+1] = p.y;
            out_pos[(size_t)q*3+2] = p.z;
            out_batch[q] = (float)b;
        }
        p.w = __uint_as_float((u32)li);
        pt[j] = p;
        atomicAdd(&hist[code[j]], 1u);
    }
    __syncthreads();
    u32 v = hist[tid];
    u32 inc = v;
    #pragma unroll
    for (int o = 1; o < 32; o <<= 1) {
        u32 t = __shfl_up_sync(0xFFFFFFFFu, inc, o);
        if ((tid & 31) >= o) inc += t;
    }
    if ((tid & 31) == 31) wsum[tid >> 5] = inc;
    __syncthreads();
    if (tid < 32) {
        u32 s = (tid < 16) ? wsum[tid] : 0u;
        u32 in2 = s;
        #pragma unroll
        for (int o = 1; o < 16; o <<= 1) {
            u32 t = __shfl_up_sync(0xFFFFFFFFu, in2, o);
            if (tid >= o) in2 += t;
        }
        if (tid < 16) wsum[tid] = in2 - s;
    }
    __syncthreads();
    hist[tid] = inc - v + wsum[tid >> 5];
    __syncthreads();
    #pragma unroll
    for (int j = 0; j < 4; j++) {
        u32 dst = atomicAdd(&hist[code[j]], 1u);
        g_sqp[qb + dst] = pt[j];
    }
}

// ---------------- hierarchical KNN ----------------
__global__ __launch_bounds__(128) void k_knn() {
    int tid = threadIdx.x, bid = blockIdx.x;
    int b  = bid >> 4;
    int t  = (bid & 15) * 128 + tid;
    int bp = b * (Np/2);
    int gb = b * NGRP;

    float4 sq = g_sqp[b * Ms + t];
    u32 oq = __float_as_uint(sq.w);
    float qxf = sq.x, qyf = sq.y, qzf = sq.z;
    u64 qx = packx2(qxf, qxf);
    u64 qy = packx2(qyf, qyf);
    u64 qz = packx2(qzf, qzf);

    u64 dd[16];
    #pragma unroll
    for (int k = 0; k < 16; k++) dd[k] = ~0ull;
    u64 kmax = ~0ull; int mp = 0;

    auto ins = [&](u64 key) {
        if (key < kmax) {
            dd[mp] = key;
            kmax = dd[0]; mp = 0;
            #pragma unroll
            for (int k = 1; k < 16; k++) if (dd[k] > kmax) { kmax = dd[k]; mp = k; }
        }
    };
    auto proc = [&](int g) {
        int base = bp + g * 32;
        #pragma unroll 4
        for (int j = 0; j < 32; j++) {
            u64 ox = g_nx[base + j], oy = g_ny[base + j], oz = g_nz[base + j];
            u64 oo = g_oi2[base + j];
            u64 dx, dy, dz, s2x, s2y, s2z, sum;
            ADDX2(dx, qx, ox);
            ADDX2(dy, qy, oy);
            ADDX2(dz, qz, oz);
            MULX2(s2x, dx, dx);
            MULX2(s2y, dy, dy);
            MULX2(s2z, dz, dz);
            ADDX2(sum, s2x, s2y);
            ADDX2(sum, sum, s2z);
            float lo, hi; unpackx2(lo, hi, sum);
            ins(((u64)__float_as_uint(lo) << 32) | (u32)oo);
            ins(((u64)__float_as_uint(hi) << 32) | (u32)(oo >> 32));
        }
    };
    auto lbof = [&](int g) {
        float4 lo = g_gbl[gb + g], hi = g_gbh[gb + g];
        float bx = fmaxf(fmaxf(lo.x - qxf, qxf - hi.x), 0.f);
        float by = fmaxf(fmaxf(lo.y - qyf, qyf - hi.y), 0.f);
        float bz = fmaxf(fmaxf(lo.z - qzf, qzf - hi.z), 0.f);
        return (bx*bx + by*by + bz*bz) * 0.999f;
    };

    float bestLB = CUDART_INF_F; int bg = 0;
    for (int g = 0; g < NGRP; g++) {
        float LB = lbof(g);
        if (LB < bestLB) { bestLB = LB; bg = g; }
    }
    int bgw = __shfl_sync(0xFFFFFFFFu, bg, 0);
    proc(bgw);

    for (int g = 0; g < NGRP; g++) {
        if (g == bgw) continue;
        float LB = lbof(g);
        bool act = __float_as_uint(LB) <= (u32)(kmax >> 32);
        if (__ballot_sync(0xFFFFFFFFu, act) == 0u) continue;
        proc(g);
    }

    int cb = b * Np;
    int qout = b * Ms + (int)oq;
    #pragma unroll
    for (int k = 0; k < 16; k++)
        g_nbr[(size_t)qout*Kn + k] = cb + (int)(dd[k] & 0xFFFFFFFFu);
}

// ---------------- gather + max-pool ----------------
__global__ __launch_bounds__(256) void k_gather(float* __restrict__ out_x) {
    int gq   = (blockIdx.x * 256 + threadIdx.x) >> 5;
    int lane = threadIdx.x & 31;
    int nb[16];
    #pragma unroll
    for (int k = 0; k < 16; k++) nb[k] = g_nbr[(size_t)gq*Kn + k];
    float4 acc = make_float4(-CUDART_INF_F, -CUDART_INF_F, -CUDART_INF_F, -CUDART_INF_F);
    #pragma unroll
    for (int k = 0; k < 16; k++) {
        float4 v = *(const float4*)(g_h + (size_t)nb[k]*COUT + lane*4);
        acc.x = fmaxf(acc.x, v.x);
        acc.y = fmaxf(acc.y, v.y);
        acc.z = fmaxf(acc.z, v.z);
        acc.w = fmaxf(acc.w, v.w);
    }
    *(float4*)(out_x + (size_t)gq*COUT + lane*4) = acc;
}

// ---------------- launch ----------------
extern "C" void kernel_launch(void* const* d_in, const int* in_sizes, int n_in,
                              void* d_out, int out_size) {
    const float* x     = (const float*)d_in[0];
    const float* pos   = (const float*)d_in[1];
    const float* W     = (const float*)d_in[3];
    const float* bias  = (const float*)d_in[4];
    const float* gamma = (const float*)d_in[5];
    const float* beta  = (const float*)d_in[6];

    float* out       = (float*)d_out;
    float* out_x     = out;
    float* out_pos   = nullptr;
    float* out_batch = nullptr;
    if (out_size >= BM*COUT + BM*3 + BM) {
        out_pos   = out + BM*COUT;
        out_batch = out + BM*COUT + BM*3;
    }

    static cudaStream_t s2 = nullptr;
    static cudaEvent_t  e0 = nullptr, e1 = nullptr, e2 = nullptr;
    if (!s2) {
        cudaStreamCreateWithFlags(&s2, cudaStreamNonBlocking);
        cudaEventCreateWithFlags(&e0, cudaEventDisableTiming);
        cudaEventCreateWithFlags(&e1, cudaEventDisableTiming);
        cudaEventCreateWithFlags(&e2, cudaEventDisableTiming);
        cudaFuncSetAttribute(k_fps,     cudaFuncAttributeMaxDynamicSharedMemorySize, FPS_SMEM);
        cudaFuncSetAttribute(k_act,     cudaFuncAttributeMaxDynamicSharedMemorySize, EXCL_SMEM);
        cudaFuncSetAttribute(k_stats,   cudaFuncAttributeMaxDynamicSharedMemorySize, EXCL_SMEM);
        cudaFuncSetAttribute(k_packgbb, cudaFuncAttributeMaxDynamicSharedMemorySize, EXCL_SMEM);
    }

    // launch 1: sort (critical path for FPS)
    k_sort  <<<Bc, 512>>>(pos);

    // fork helper chain onto s2 (all excluded from FPS SMs by smem footprint)
    cudaEventRecord(e0, 0);
    cudaStreamWaitEvent(s2, e0, 0);
    k_packgbb <<<Bc*NGRP/4, 128, EXCL_SMEM, s2>>>();            // launch 2
    cudaEventRecord(e2, s2);                                    // knn dep
    k_gemm  <<<NBLK_GEMM, 256, 0, s2>>>(x, W, bias);            // launch 3
    k_stats <<<1, COUT, EXCL_SMEM, s2>>>(gamma, beta);          // launch 4
    k_act   <<<(BNr*COUT/4)/256, 256, EXCL_SMEM, s2>>>();       // launch 5
    cudaEventRecord(e1, s2);                                    // gather dep

    // launch 6: FPS (ncu -s 5 -c 1 profiles this)
    k_fps   <<<Bc, 512, FPS_SMEM>>>();

    k_qsort <<<Bc, 512>>>(out_pos, out_batch);                  // launch 7
    cudaStreamWaitEvent(0, e2, 0);
    k_knn   <<<Bc*16, 128>>>();                                 // launch 8
    cudaStreamWaitEvent(0, e1, 0);
    k_gather<<<BM/8, 256>>>(out_x);                             // launch 9
}

// round 17
// speedup vs baseline: 1.2879x; 1.0959x over previous
#include <cuda_runtime.h>
#include <math_constants.h>
#include <cstdint>

#define Bc    8
#define Np    4096
#define Ms    2048
#define Kn    16
#define CIN   64
#define COUT  128
#define BNr   (Bc*Np)     // 32768
#define BM    (Bc*Ms)     // 16384
#define NBLK_GEMM 256
#define NGRP  64
#define FPS_SMEM  200704   // 196KB: excludes any co-resident smem-using block
#define EXCL_SMEM 65536    // dummy smem: keeps helper kernels off FPS SMs

typedef unsigned long long u64;
typedef unsigned int u32;

#define ADDX2(o,a,b) asm("add.rn.f32x2 %0,%1,%2;" : "=l"(o) : "l"(a), "l"(b))
#define MULX2(o,a,b) asm("mul.rn.f32x2 %0,%1,%2;" : "=l"(o) : "l"(a), "l"(b))
__device__ __forceinline__ u64 packx2(float lo, float hi) {
    u64 o; asm("mov.b64 %0,{%1,%2};" : "=l"(o) : "f"(lo), "f"(hi)); return o;
}
__device__ __forceinline__ void unpackx2(float& lo, float& hi, u64 v) {
    asm("mov.b64 {%0,%1},%2;" : "=f"(lo), "=f"(hi) : "l"(v));
}

// ---------------- device scratch ----------------
__device__ float  g_h[BNr*COUT];
__device__ float  g_part[NBLK_GEMM*COUT*2];
__device__ float  g_scale[COUT];
__device__ float  g_shift[COUT];
__device__ float4 g_spos4[BNr];              // Morton-sorted, w = orig local idx
__device__ u64    g_nx[BNr/2];
__device__ u64    g_ny[BNr/2];
__device__ u64    g_nz[BNr/2];
__device__ u64    g_oi2[BNr/2];
__device__ float4 g_gbl[Bc*NGRP];
__device__ float4 g_gbh[Bc*NGRP];
__device__ float4 g_qpos[BM];
__device__ float4 g_sqp[BM];
__device__ int    g_nbr[BM*Kn];

// ---------------- Morton helpers ----------------
__device__ __forceinline__ u32 mort3(u32 v) { return (v & 1u) | ((v & 2u) << 2) | ((v & 4u) << 4); }
__device__ __forceinline__ u32 mcode(float x, float y, float z) {
    int cx = min(7, max(0, (int)(x * 8.f)));
    int cy = min(7, max(0, (int)(y * 8.f)));
    int cz = min(7, max(0, (int)(z * 8.f)));
    return (mort3((u32)cx) << 2) | (mort3((u32)cy) << 1) | mort3((u32)cz);
}

// ---------------- Morton counting sort (reads pos directly; emits first sample) ----------------
__global__ __launch_bounds__(512) void k_sort(const float* __restrict__ pos) {
    __shared__ u32 hist[512];
    __shared__ u32 wsum[16];
    int tid = threadIdx.x, b = blockIdx.x, cb = b * Np;
    hist[tid] = 0;
    __syncthreads();
    float4 pt[8]; u32 code[8];
    #pragma unroll
    for (int j = 0; j < 8; j++) {
        int li = j * 512 + tid;
        const float* pp = pos + (size_t)(cb + li) * 3;
        float4 p = make_float4(pp[0], pp[1], pp[2], __uint_as_float((u32)li));
        code[j] = mcode(p.x, p.y, p.z);
        pt[j] = p;
        atomicAdd(&hist[code[j]], 1u);
        if (li == 0) g_qpos[b * Ms] = p;     // FPS seed = original index 0
    }
    __syncthreads();
    u32 v = hist[tid];
    u32 inc = v;
    #pragma unroll
    for (int o = 1; o < 32; o <<= 1) {
        u32 t = __shfl_up_sync(0xFFFFFFFFu, inc, o);
        if ((tid & 31) >= o) inc += t;
    }
    if ((tid & 31) == 31) wsum[tid >> 5] = inc;
    __syncthreads();
    if (tid < 32) {
        u32 s = (tid < 16) ? wsum[tid] : 0u;
        u32 in2 = s;
        #pragma unroll
        for (int o = 1; o < 16; o <<= 1) {
            u32 t = __shfl_up_sync(0xFFFFFFFFu, in2, o);
            if (tid >= o) in2 += t;
        }
        if (tid < 16) wsum[tid] = in2 - s;
    }
    __syncthreads();
    hist[tid] = inc - v + wsum[tid >> 5];
    __syncthreads();
    #pragma unroll
    for (int j = 0; j < 8; j++) {
        u32 dst = atomicAdd(&hist[code[j]], 1u);
        g_spos4[cb + dst] = pt[j];
    }
}

// ---------------- fused pack + group bbox: warp per 64-pt group ----------------
__global__ __launch_bounds__(128) void k_packgbb() {
    extern __shared__ char dummy3[];         // occupancy shaping only
    int wid = threadIdx.x >> 5, lane = threadIdx.x & 31;
    int g = blockIdx.x * 4 + wid;            // 0..Bc*NGRP-1
    int pb = g * 32 + lane;                  // pair index
    float4 p0 = g_spos4[2*pb], p1 = g_spos4[2*pb + 1];
    g_nx[pb]  = packx2(-p0.x, -p1.x);
    g_ny[pb]  = packx2(-p0.y, -p1.y);
    g_nz[pb]  = packx2(-p0.z, -p1.z);
    g_oi2[pb] = ((u64)__float_as_uint(p1.w) << 32) | __float_as_uint(p0.w);
    // bbox: coords in [0,1) => float bits order as u32
    u32 lx = __reduce_min_sync(0xFFFFFFFFu, __float_as_uint(fminf(p0.x, p1.x)));
    u32 ly = __reduce_min_sync(0xFFFFFFFFu, __float_as_uint(fminf(p0.y, p1.y)));
    u32 lz = __reduce_min_sync(0xFFFFFFFFu, __float_as_uint(fminf(p0.z, p1.z)));
    u32 hx = __reduce_max_sync(0xFFFFFFFFu, __float_as_uint(fmaxf(p0.x, p1.x)));
    u32 hy = __reduce_max_sync(0xFFFFFFFFu, __float_as_uint(fmaxf(p0.y, p1.y)));
    u32 hz = __reduce_max_sync(0xFFFFFFFFu, __float_as_uint(fmaxf(p0.z, p1.z)));
    if (lane == 0) {
        g_gbl[g] = make_float4(__uint_as_float(lx), __uint_as_float(ly), __uint_as_float(lz), 0.f);
        g_gbh[g] = make_float4(__uint_as_float(hx), __uint_as_float(hy), __uint_as_float(hz), 0.f);
    }
}

// ---------------- GEMM + BN partials ----------------
__global__ __launch_bounds__(256) void k_gemm(const float* __restrict__ x,
                                              const float* __restrict__ W,
                                              const float* __restrict__ bias) {
    __shared__ float sW[CIN*COUT];
    __shared__ float sx[32*CIN];
    __shared__ float sred[256*8];
    int tid = threadIdx.x;

    const float4* W4 = (const float4*)W;
    float4* sW4 = (float4*)sW;
    #pragma unroll
    for (int i = 0; i < 8; i++) sW4[tid + i*256] = W4[tid + i*256];

    int c4   = (tid & 31) * 4;
    int wrow = (tid >> 5) * 4;
    float4 bv = *(const float4*)(bias + c4);

    float s0=0.f,s1=0.f,s2=0.f,s3=0.f, q0=0.f,q1=0.f,q2=0.f,q3=0.f;
    int rowblk = blockIdx.x * 128;

    for (int sub = 0; sub < 4; sub++) {
        __syncthreads();
        int r0 = rowblk + sub*32;
        const float4* xg = (const float4*)(x + (size_t)r0 * CIN);
        float4* sx4 = (float4*)sx;
        sx4[tid]       = xg[tid];
        sx4[tid + 256] = xg[tid + 256];
        __syncthreads();

        float a[4][4];
        #pragma unroll
        for (int r = 0; r < 4; r++) { a[r][0]=bv.x; a[r][1]=bv.y; a[r][2]=bv.z; a[r][3]=bv.w; }
        #pragma unroll 8
        for (int k = 0; k < CIN; k++) {
            float4 w4 = *(float4*)(sW + k*COUT + c4);
            #pragma unroll
            for (int r = 0; r < 4; r++) {
                float xv = sx[(wrow + r)*CIN + k];
                a[r][0] = fmaf(xv, w4.x, a[r][0]);
                a[r][1] = fmaf(xv, w4.y, a[r][1]);
                a[r][2] = fmaf(xv, w4.z, a[r][2]);
                a[r][3] = fmaf(xv, w4.w, a[r][3]);
            }
        }
        #pragma unroll
        for (int r = 0; r < 4; r++) {
            int row = r0 + wrow + r;
            *(float4*)(g_h + (size_t)row*COUT + c4) =
                make_float4(a[r][0], a[r][1], a[r][2], a[r][3]);
            s0 += a[r][0]; s1 += a[r][1]; s2 += a[r][2]; s3 += a[r][3];
            q0 = fmaf(a[r][0], a[r][0], q0);
            q1 = fmaf(a[r][1], a[r][1], q1);
            q2 = fmaf(a[r][2], a[r][2], q2);
            q3 = fmaf(a[r][3], a[r][3], q3);
        }
    }
    float* rp = sred + tid*8;
    rp[0]=s0; rp[1]=s1; rp[2]=s2; rp[3]=s3; rp[4]=q0; rp[5]=q1; rp[6]=q2; rp[7]=q3;
    __syncthreads();
    if (tid < 32) {
        float ss[4] = {0,0,0,0}, qq[4] = {0,0,0,0};
        for (int w = 0; w < 8; w++) {
            float* p = sred + (w*32 + tid)*8;
            #pragma unroll
            for (int i = 0; i < 4; i++) { ss[i] += p[i]; qq[i] += p[4+i]; }
        }
        #pragma unroll
        for (int i = 0; i < 4; i++) {
            int c = tid*4 + i;
            g_part[(blockIdx.x*COUT + c)*2 + 0] = ss[i];
            g_part[(blockIdx.x*COUT + c)*2 + 1] = qq[i];
        }
    }
}

__global__ void k_stats(const float* __restrict__ gamma, const float* __restrict__ beta) {
    extern __shared__ char dummy1[];
    int c = threadIdx.x;
    float s = 0.f, q = 0.f;
    for (int b = 0; b < NBLK_GEMM; b++) {
        s += g_part[(b*COUT + c)*2 + 0];
        q += g_part[(b*COUT + c)*2 + 1];
    }
    float mu   = s * (1.0f / BNr);
    float var  = q * (1.0f / BNr) - mu*mu;
    float rstd = rsqrtf(var + 1e-5f);
    float sc   = gamma[c] * rstd;
    g_scale[c] = sc;
    g_shift[c] = beta[c] - mu * sc;
}

__global__ __launch_bounds__(256) void k_act() {
    extern __shared__ char dummy2[];
    int i = blockIdx.x * 256 + threadIdx.x;
    float4 h = ((float4*)g_h)[i];
    int c4 = (i & 31) * 4;
    float4 sc = *(float4*)(g_scale + c4);
    float4 sh = *(float4*)(g_shift + c4);
    float y0 = fmaf(h.x, sc.x, sh.x);
    float y1 = fmaf(h.y, sc.y, sh.y);
    float y2 = fmaf(h.z, sc.z, sh.z);
    float y3 = fmaf(h.w, sc.w, sh.w);
    const float is2 = 0.70710678118654752f;
    h.x = 0.5f * y0 * (1.f + erff(y0 * is2));
    h.y = 0.5f * y1 * (1.f + erff(y1 * is2));
    h.z = 0.5f * y2 * (1.f + erff(y2 * is2));
    h.w = 0.5f * y3 * (1.f + erff(y3 * is2));
    ((float4*)g_h)[i] = h;
}

// ---------------- pruned FPS (R7 topology): 512 thr, cached warp keys, two-stage redux ----------------
// Winner slots recorded in smem history; g_qpos dumped once at kernel end.
__global__ __launch_bounds__(512) void k_fps() {
    extern __shared__ char fsm[];
    float4* s_pts  = (float4*)fsm;                 // 4096 float4 = 64KB
    u64*    s_wkey = (u64*)(fsm + Np*16);          // 2 x 16 keys (256B)
    u32*    s_hist = (u32*)(fsm + Np*16 + 256);    // Ms winner slots (8KB)
    int tid = threadIdx.x, b = blockIdx.x, cb = b * Np;
    int lane = tid & 31, w = tid >> 5;

    float dm[8]; u32 cij[8];                 // cij = ((4095-oi)<<12)|slot  (invariant)
    u64 npx[4], npy[4], npz[4];
    float lox =  CUDART_INF_F, loy =  CUDART_INF_F, loz =  CUDART_INF_F;
    float hix = -CUDART_INF_F, hiy = -CUDART_INF_F, hiz = -CUDART_INF_F;
    {
        float tx[8], ty[8], tz[8];
        #pragma unroll
        for (int j = 0; j < 8; j++) {
            float4 p = g_spos4[cb + tid*8 + j];
            s_pts[tid*8 + j] = p;
            tx[j] = p.x; ty[j] = p.y; tz[j] = p.z;
            cij[j] = ((4095u - __float_as_uint(p.w)) << 12) | (u32)(tid*8 + j);
            dm[j] = CUDART_INF_F;
            lox = fminf(lox, p.x); hix = fmaxf(hix, p.x);
            loy = fminf(loy, p.y); hiy = fmaxf(hiy, p.y);
            loz = fminf(loz, p.z); hiz = fmaxf(hiz, p.z);
        }
        #pragma unroll
        for (int p = 0; p < 4; p++) {
            npx[p] = packx2(-tx[2*p], -tx[2*p+1]);
            npy[p] = packx2(-ty[2*p], -ty[2*p+1]);
            npz[p] = packx2(-tz[2*p], -tz[2*p+1]);
        }
    }
    float gmaxd = CUDART_INF_F;
    u64 wkey = 0;                             // cached warp key

    float4 a4 = g_qpos[b * Ms];               // seed written by k_sort
    float ax = a4.x, ay = a4.y, az = a4.z;
    __syncthreads();                          // s_pts visible before winner LDS

    for (int m = 1; m < Ms; m++) {
        float bx = fmaxf(fmaxf(lox - ax, ax - hix), 0.f);
        float by = fmaxf(fmaxf(loy - ay, ay - hiy), 0.f);
        float bz = fmaxf(fmaxf(loz - az, az - hiz), 0.f);
        float LB = (bx*bx + by*by + bz*bz) * 0.999f;
        bool active = (LB < gmaxd);
        u32 aball = __ballot_sync(0xFFFFFFFFu, active);
        if (aball) {                          // some lane changed: recompute warp key
            if (active) {
                u64 pax = packx2(ax, ax), pay = packx2(ay, ay), paz = packx2(az, az);
                #pragma unroll
                for (int p = 0; p < 4; p++) {
                    u64 dx, dy, dz, s2x, s2y, s2z, s;
                    ADDX2(dx, pax, npx[p]);
                    ADDX2(dy, pay, npy[p]);
                    ADDX2(dz, paz, npz[p]);
                    MULX2(s2x, dx, dx);
                    MULX2(s2y, dy, dy);
                    MULX2(s2z, dz, dz);
                    ADDX2(s, s2x, s2y);
                    ADDX2(s, s, s2z);
                    float lo, hi; unpackx2(lo, hi, s);
                    dm[2*p]   = fminf(dm[2*p],   lo);
                    dm[2*p+1] = fminf(dm[2*p+1], hi);
                }
                float m01 = fmaxf(dm[0], dm[1]), m23 = fmaxf(dm[2], dm[3]);
                float m45 = fmaxf(dm[4], dm[5]), m67 = fmaxf(dm[6], dm[7]);
                gmaxd = fmaxf(fmaxf(m01, m23), fmaxf(m45, m67));
            }
            u32 db = __float_as_uint(gmaxd);
            u32 bd = __reduce_max_sync(0xFFFFFFFFu, db);
            u32 cand = 0u;
            if (db == bd) {
                #pragma unroll
                for (int j = 0; j < 8; j++)
                    cand = max(cand, (dm[j] == gmaxd) ? cij[j] : 0u);
            }
            u32 bi = __reduce_max_sync(0xFFFFFFFFu, cand);
            wkey = ((u64)bd << 32) | bi;
        }
        if (lane == 0) s_wkey[(m & 1)*16 + w] = wkey;
        __syncthreads();
        u64 kk  = s_wkey[(m & 1)*16 + (lane & 15)];
        u32 hb  = (u32)(kk >> 32);
        u32 bd2 = __reduce_max_sync(0xFFFFFFFFu, hb);
        u32 c2  = (hb == bd2) ? (u32)kk : 0u;
        u32 wi  = __reduce_max_sync(0xFFFFFFFFu, c2);
        int spos = (int)(wi & 0xFFFu);
        if (tid == 0) s_hist[m] = (u32)spos;  // STS only; gmem dump deferred
        float4 p = s_pts[spos];               // LDS broadcast
        ax = p.x; ay = p.y; az = p.z;
    }
    __syncthreads();                          // history complete
    #pragma unroll
    for (int j = 0; j < 4; j++) {             // dump samples 1..Ms-1
        int m = tid * 4 + j;
        if (m >= 1) g_qpos[b * Ms + m] = s_pts[s_hist[m]];
    }
}

// ---------------- query Morton sort + output emit (fused) ----------------
__global__ __launch_bounds__(512) void k_qsort(float* __restrict__ out_pos,
                                               float* __restrict__ out_batch) {
    __shared__ u32 hist[512];
    __shared__ u32 wsum[16];
    int tid = threadIdx.x, b = blockIdx.x, qb = b * Ms;
    hist[tid] = 0;
    __syncthreads();
    float4 pt[4]; u32 code[4];
    #pragma unroll
    for (int j = 0; j < 4; j++) {
        int li = j * 512 + tid;
        float4 p = g_qpos[qb + li];
        code[j] = mcode(p.x, p.y, p.z);
        if (out_pos) {
            int q = qb + li;
            out_pos[(size_t)q*3+0] = p.x;
            out_pos[(size_t)q*3+1] = p.y;
            out_pos[(size_t)q*3+2] = p.z;
            out_batch[q] = (float)b;
        }
        p.w = __uint_as_float((u32)li);
        pt[j] = p;
        atomicAdd(&hist[code[j]], 1u);
    }
    __syncthreads();
    u32 v = hist[tid];
    u32 inc = v;
    #pragma unroll
    for (int o = 1; o < 32; o <<= 1) {
        u32 t = __shfl_up_sync(0xFFFFFFFFu, inc, o);
        if ((tid & 31) >= o) inc += t;
    }
    if ((tid & 31) == 31) wsum[tid >> 5] = inc;
    __syncthreads();
    if (tid < 32) {
        u32 s = (tid < 16) ? wsum[tid] : 0u;
        u32 in2 = s;
        #pragma unroll
        for (int o = 1; o < 16; o <<= 1) {
            u32 t = __shfl_up_sync(0xFFFFFFFFu, in2, o);
            if (tid >= o) in2 += t;
        }
        if (tid < 16) wsum[tid] = in2 - s;
    }
    __syncthreads();
    hist[tid] = inc - v + wsum[tid >> 5];
    __syncthreads();
    #pragma unroll
    for (int j = 0; j < 4; j++) {
        u32 dst = atomicAdd(&hist[code[j]], 1u);
        g_sqp[qb + dst] = pt[j];
    }
}

// ---------------- hierarchical KNN ----------------
__global__ __launch_bounds__(128) void k_knn() {
    int tid = threadIdx.x, bid = blockIdx.x;
    int b  = bid >> 4;
    int t  = (bid & 15) * 128 + tid;
    int bp = b * (Np/2);
    int gb = b * NGRP;

    float4 sq = g_sqp[b * Ms + t];
    u32 oq = __float_as_uint(sq.w);
    float qxf = sq.x, qyf = sq.y, qzf = sq.z;
    u64 qx = packx2(qxf, qxf);
    u64 qy = packx2(qyf, qyf);
    u64 qz = packx2(qzf, qzf);

    u64 dd[16];
    #pragma unroll
    for (int k = 0; k < 16; k++) dd[k] = ~0ull;
    u64 kmax = ~0ull; int mp = 0;

    auto ins = [&](u64 key) {
        if (key < kmax) {
            dd[mp] = key;
            kmax = dd[0]; mp = 0;
            #pragma unroll
            for (int k = 1; k < 16; k++) if (dd[k] > kmax) { kmax = dd[k]; mp = k; }
        }
    };
    auto proc = [&](int g) {
        int base = bp + g * 32;
        #pragma unroll 4
        for (int j = 0; j < 32; j++) {
            u64 ox = g_nx[base + j], oy = g_ny[base + j], oz = g_nz[base + j];
            u64 oo = g_oi2[base + j];
            u64 dx, dy, dz, s2x, s2y, s2z, sum;
            ADDX2(dx, qx, ox);
            ADDX2(dy, qy, oy);
            ADDX2(dz, qz, oz);
            MULX2(s2x, dx, dx);
            MULX2(s2y, dy, dy);
            MULX2(s2z, dz, dz);
            ADDX2(sum, s2x, s2y);
            ADDX2(sum, sum, s2z);
            float lo, hi; unpackx2(lo, hi, sum);
            ins(((u64)__float_as_uint(lo) << 32) | (u32)oo);
            ins(((u64)__float_as_uint(hi) << 32) | (u32)(oo >> 32));
        }
    };
    auto lbof = [&](int g) {
        float4 lo = g_gbl[gb + g], hi = g_gbh[gb + g];
        float bx = fmaxf(fmaxf(lo.x - qxf, qxf - hi.x), 0.f);
        float by = fmaxf(fmaxf(lo.y - qyf, qyf - hi.y), 0.f);
        float bz = fmaxf(fmaxf(lo.z - qzf, qzf - hi.z), 0.f);
        return (bx*bx + by*by + bz*bz) * 0.999f;
    };

    float bestLB = CUDART_INF_F; int bg = 0;
    for (int g = 0; g < NGRP; g++) {
        float LB = lbof(g);
        if (LB < bestLB) { bestLB = LB; bg = g; }
    }
    int bgw = __shfl_sync(0xFFFFFFFFu, bg, 0);
    proc(bgw);

    for (int g = 0; g < NGRP; g++) {
        if (g == bgw) continue;
        float LB = lbof(g);
        bool act = __float_as_uint(LB) <= (u32)(kmax >> 32);
        if (__ballot_sync(0xFFFFFFFFu, act) == 0u) continue;
        proc(g);
    }

    int cb = b * Np;
    int qout = b * Ms + (int)oq;
    #pragma unroll
    for (int k = 0; k < 16; k++)
        g_nbr[(size_t)qout*Kn + k] = cb + (int)(dd[k] & 0xFFFFFFFFu);
}

// ---------------- gather + max-pool ----------------
__global__ __launch_bounds__(256) void k_gather(float* __restrict__ out_x) {
    int gq   = (blockIdx.x * 256 + threadIdx.x) >> 5;
    int lane = threadIdx.x & 31;
    int nb[16];
    #pragma unroll
    for (int k = 0; k < 16; k++) nb[k] = g_nbr[(size_t)gq*Kn + k];
    float4 acc = make_float4(-CUDART_INF_F, -CUDART_INF_F, -CUDART_INF_F, -CUDART_INF_F);
    #pragma unroll
    for (int k = 0; k < 16; k++) {
        float4 v = *(const float4*)(g_h + (size_t)nb[k]*COUT + lane*4);
        acc.x = fmaxf(acc.x, v.x);
        acc.y = fmaxf(acc.y, v.y);
        acc.z = fmaxf(acc.z, v.z);
        acc.w = fmaxf(acc.w, v.w);
    }
    *(float4*)(out_x + (size_t)gq*COUT + lane*4) = acc;
}

// ---------------- launch ----------------
extern "C" void kernel_launch(void* const* d_in, const int* in_sizes, int n_in,
                              void* d_out, int out_size) {
    const float* x     = (const float*)d_in[0];
    const float* pos   = (const float*)d_in[1];
    const float* W     = (const float*)d_in[3];
    const float* bias  = (const float*)d_in[4];
    const float* gamma = (const float*)d_in[5];
    const float* beta  = (const float*)d_in[6];

    float* out       = (float*)d_out;
    float* out_x     = out;
    float* out_pos   = nullptr;
    float* out_batch = nullptr;
    if (out_size >= BM*COUT + BM*3 + BM) {
        out_pos   = out + BM*COUT;
        out_batch = out + BM*COUT + BM*3;
    }

    static cudaStream_t s2 = nullptr;
    static cudaEvent_t  e0 = nullptr, e1 = nullptr, e2 = nullptr;
    if (!s2) {
        cudaStreamCreateWithFlags(&s2, cudaStreamNonBlocking);
        cudaEventCreateWithFlags(&e0, cudaEventDisableTiming);
        cudaEventCreateWithFlags(&e1, cudaEventDisableTiming);
        cudaEventCreateWithFlags(&e2, cudaEventDisableTiming);
        cudaFuncSetAttribute(k_fps,     cudaFuncAttributeMaxDynamicSharedMemorySize, FPS_SMEM);
        cudaFuncSetAttribute(k_act,     cudaFuncAttributeMaxDynamicSharedMemorySize, EXCL_SMEM);
        cudaFuncSetAttribute(k_stats,   cudaFuncAttributeMaxDynamicSharedMemorySize, EXCL_SMEM);
        cudaFuncSetAttribute(k_packgbb, cudaFuncAttributeMaxDynamicSharedMemorySize, EXCL_SMEM);
    }

    // critical path first: sort -> fps. FPS submitted BEFORE the helper grids so
    // its 8 blocks (196KB smem each) claim clean SMs before k_act floods the chip.
    k_sort  <<<Bc, 512>>>(pos);                                 // launch 1
    cudaEventRecord(e0, 0);
    k_fps   <<<Bc, 512, FPS_SMEM>>>();                          // launch 2

    // helpers fork onto s2 after sort; excluded from FPS SMs by smem footprint
    cudaStreamWaitEvent(s2, e0, 0);
    k_packgbb <<<Bc*NGRP/4, 128, EXCL_SMEM, s2>>>();            // launch 3
    cudaEventRecord(e2, s2);                                    // knn dep
    k_gemm  <<<NBLK_GEMM, 256, 0, s2>>>(x, W, bias);            // launch 4
    k_stats <<<1, COUT, EXCL_SMEM, s2>>>(gamma, beta);          // launch 5
    k_act   <<<(BNr*COUT/4)/256, 256, EXCL_SMEM, s2>>>();       // launch 6
    cudaEventRecord(e1, s2);                                    // gather dep

    k_qsort <<<Bc, 512>>>(out_pos, out_batch);                  // launch 7
    cudaStreamWaitEvent(0, e2, 0);
    k_knn   <<<Bc*16, 128>>>();                                 // launch 8
    cudaStreamWaitEvent(0, e1, 0);
    k_gather<<<BM/8, 256>>>(out_x);                             // launch 9
}